// round 15
// baseline (speedup 1.0000x reference)
#include <cuda_runtime.h>
#include <cuda_bf16.h>
#include <cstdint>

// Sparse average pooling, output-driven two-phase:
//   Phase A: memset node zeroes per-output counters
//   Phase B: invert rulebook into fixed-capacity buckets (4 rules/thread)
//   Phase C: gather with WARP-PER-ROW mapping: 32 threads x float2 per output
//            row -> zero intra-warp divergence (all lanes share n), 64-thread
//            blocks -> 2-row retirement granularity.
// Locked lessons: __ldg on input gathers; gather is store-free except output;
// CAP=24 (overflow P ~1e-12/row, guard retained).

#define CAP 24                     // 96B per row, 16B-aligned
#define NOUT_CAP 400000
#define NRULE_CAP 1600000

__device__ int g_counts[NOUT_CAP];
__device__ int g_bucket[(size_t)NOUT_CAP * CAP];

__global__ void bucket_scatter_kernel(const int* __restrict__ rules_in,
                                      const int* __restrict__ rules_out,
                                      int n_rules)
{
    int t = blockIdx.x * blockDim.x + threadIdx.x;
    int base = t * 4;
    if (base >= n_rules) return;

    if (base + 4 <= n_rules) {
        int4 ri = *reinterpret_cast<const int4*>(rules_in  + base);
        int4 ro = *reinterpret_cast<const int4*>(rules_out + base);
        int s;
        s = atomicAdd(&g_counts[ro.x], 1); if (s < CAP) g_bucket[(size_t)ro.x * CAP + s] = ri.x;
        s = atomicAdd(&g_counts[ro.y], 1); if (s < CAP) g_bucket[(size_t)ro.y * CAP + s] = ri.y;
        s = atomicAdd(&g_counts[ro.z], 1); if (s < CAP) g_bucket[(size_t)ro.z * CAP + s] = ri.z;
        s = atomicAdd(&g_counts[ro.w], 1); if (s < CAP) g_bucket[(size_t)ro.w * CAP + s] = ri.w;
    } else {
        for (int r = base; r < n_rules; r++) {
            int ro = rules_out[r];
            int s = atomicAdd(&g_counts[ro], 1);
            if (s < CAP) g_bucket[(size_t)ro * CAP + s] = rules_in[r];
        }
    }
}

__global__ void __launch_bounds__(64)
gather_kernel(const float* __restrict__ input,
              float* __restrict__ out,
              int n_out)
{
    const float scale = 0.125f;   // 1 / POOL_VOLUME

    long long gid = (long long)blockIdx.x * blockDim.x + threadIdx.x;
    int o = (int)(gid >> 5);      // output row (one warp per row)
    int c = (int)(gid & 31);      // float2 chunk (0..31)
    if (o >= n_out) return;

    int n = g_counts[o];          // uniform across the warp -> no divergence
    if (n > CAP) n = CAP;

    const int4* bk4 = reinterpret_cast<const int4*>(g_bucket + (size_t)o * CAP);
    const float2* in2 = reinterpret_cast<const float2*>(input);

    float2 acc = make_float2(0.f, 0.f);

    // 4 contributing rows per group: one broadcast int4 index load,
    // 4 independent 8B gathers per lane (warp: 256B = 2 lines per rule row).
    for (int base = 0; base < n; base += 4) {
        int4 idx = __ldcs(bk4 + (base >> 2));
        int m = n - base;

        float2 v0, v1, v2, v3;
        bool p1 = (m > 1), p2 = (m > 2), p3 = (m > 3);
        v0 = __ldg(in2 + (size_t)idx.x * 32 + c);
        if (p1) v1 = __ldg(in2 + (size_t)idx.y * 32 + c);
        if (p2) v2 = __ldg(in2 + (size_t)idx.z * 32 + c);
        if (p3) v3 = __ldg(in2 + (size_t)idx.w * 32 + c);

        acc.x += v0.x; acc.y += v0.y;
        if (p1) { acc.x += v1.x; acc.y += v1.y; }
        if (p2) { acc.x += v2.x; acc.y += v2.y; }
        if (p3) { acc.x += v3.x; acc.y += v3.y; }
    }
    acc.x *= scale; acc.y *= scale;

    __stcs(reinterpret_cast<float2*>(out + (size_t)o * 64) + c, acc);
}

// Fallback path (direct atomic scatter) if sizes exceed scratch capacity.
__global__ void avgpool_scatter_kernel(const float* __restrict__ input,
                                       const int* __restrict__ rules_in,
                                       const int* __restrict__ rules_out,
                                       float* __restrict__ out,
                                       int n_rules)
{
    const float scale = 0.125f;
    long long gid = (long long)blockIdx.x * blockDim.x + threadIdx.x;
    long long total = (long long)n_rules * 16;
    if (gid >= total) return;
    int r = (int)(gid >> 4);
    int c = (int)(gid & 15);
    int rin = rules_in[r];
    int rout = rules_out[r];
    const float4* src = reinterpret_cast<const float4*>(input + (long long)rin * 64) + c;
    float4 v = *src;
    v.x *= scale; v.y *= scale; v.z *= scale; v.w *= scale;
    float* dst = out + (long long)rout * 64 + c * 4;
    asm volatile("red.global.add.v4.f32 [%0], {%1, %2, %3, %4};"
                 :: "l"(dst), "f"(v.x), "f"(v.y), "f"(v.z), "f"(v.w) : "memory");
}

extern "C" void kernel_launch(void* const* d_in, const int* in_sizes, int n_in,
                              void* d_out, int out_size)
{
    const float* input     = (const float*)d_in[0];
    const int*   rules_in  = (const int*)d_in[1];
    const int*   rules_out = (const int*)d_in[2];
    float* out = (float*)d_out;

    int n_rules = in_sizes[1];
    int n_out   = out_size / 64;

    if (n_out > NOUT_CAP || n_rules > NRULE_CAP) {
        cudaMemsetAsync(out, 0, (size_t)out_size * sizeof(float));
        long long total = (long long)n_rules * 16;
        int threads = 256;
        long long blocks = (total + threads - 1) / threads;
        avgpool_scatter_kernel<<<(unsigned)blocks, threads>>>(
            input, rules_in, rules_out, out, n_rules);
        return;
    }

    // Phase A: zero counters via a memset node.
    {
        void* counts_ptr = nullptr;
        cudaGetSymbolAddress(&counts_ptr, g_counts);
        cudaMemsetAsync(counts_ptr, 0, (size_t)n_out * sizeof(int));
    }

    // Phase B: invert rulebook (4 rules per thread)
    {
        int n_t = (n_rules + 3) / 4;
        int threads = 256;
        int blocks = (n_t + threads - 1) / threads;
        bucket_scatter_kernel<<<blocks, threads>>>(rules_in, rules_out, n_rules);
    }

    // Phase C: warp-per-row gather (32 threads x float2), 64-thread blocks
    {
        long long total = (long long)n_out * 32;
        int threads = 64;
        long long blocks = (total + threads - 1) / threads;
        gather_kernel<<<(unsigned)blocks, threads>>>(input, out, n_out);
    }
}

// round 16
// speedup vs baseline: 1.2880x; 1.2880x over previous
#include <cuda_runtime.h>
#include <cuda_bf16.h>
#include <cstdint>

// Sparse average pooling, output-driven two-phase:
//   Phase A: memset node zeroes g_meta (12MB: count + 7 inline slots per row)
//   Phase B: invert rulebook; count and first 7 indices live in ONE 32B
//            sector per output row; rare spill (P~5%) to overflow array
//   Phase C: gather, 16 threads x float4 per row (proven shape), 128-thd
//            blocks; metadata = single-sector read (1 serial level).
// Locked lessons: __ldg float4 input gathers (not float2, not .cg); gather
// store-free except output row.

#define INLINE_SLOTS 7              // meta row: [count, idx0..idx6] = 32B
#define OVF_CAP 24                  // overflow slots; total cap 31, P(>31)~1e-15
#define NOUT_CAP 400000
#define NRULE_CAP 1600000

__device__ int g_meta[(size_t)NOUT_CAP * 8];          // 12.8 MB
__device__ int g_ovf [(size_t)NOUT_CAP * OVF_CAP];    // touched by ~5% of rows

__global__ void bucket_scatter_kernel(const int* __restrict__ rules_in,
                                      const int* __restrict__ rules_out,
                                      int n_rules)
{
    int t = blockIdx.x * blockDim.x + threadIdx.x;
    int base = t * 4;
    if (base >= n_rules) return;

    if (base + 4 <= n_rules) {
        int4 ri = *reinterpret_cast<const int4*>(rules_in  + base);
        int4 ro = *reinterpret_cast<const int4*>(rules_out + base);
        int s;
        s = atomicAdd(&g_meta[(size_t)ro.x * 8], 1);
        if (s < INLINE_SLOTS) g_meta[(size_t)ro.x * 8 + 1 + s] = ri.x;
        else if (s < INLINE_SLOTS + OVF_CAP) g_ovf[(size_t)ro.x * OVF_CAP + s - INLINE_SLOTS] = ri.x;
        s = atomicAdd(&g_meta[(size_t)ro.y * 8], 1);
        if (s < INLINE_SLOTS) g_meta[(size_t)ro.y * 8 + 1 + s] = ri.y;
        else if (s < INLINE_SLOTS + OVF_CAP) g_ovf[(size_t)ro.y * OVF_CAP + s - INLINE_SLOTS] = ri.y;
        s = atomicAdd(&g_meta[(size_t)ro.z * 8], 1);
        if (s < INLINE_SLOTS) g_meta[(size_t)ro.z * 8 + 1 + s] = ri.z;
        else if (s < INLINE_SLOTS + OVF_CAP) g_ovf[(size_t)ro.z * OVF_CAP + s - INLINE_SLOTS] = ri.z;
        s = atomicAdd(&g_meta[(size_t)ro.w * 8], 1);
        if (s < INLINE_SLOTS) g_meta[(size_t)ro.w * 8 + 1 + s] = ri.w;
        else if (s < INLINE_SLOTS + OVF_CAP) g_ovf[(size_t)ro.w * OVF_CAP + s - INLINE_SLOTS] = ri.w;
    } else {
        for (int r = base; r < n_rules; r++) {
            int ro = rules_out[r];
            int s = atomicAdd(&g_meta[(size_t)ro * 8], 1);
            if (s < INLINE_SLOTS) g_meta[(size_t)ro * 8 + 1 + s] = rules_in[r];
            else if (s < INLINE_SLOTS + OVF_CAP) g_ovf[(size_t)ro * OVF_CAP + s - INLINE_SLOTS] = rules_in[r];
        }
    }
}

__global__ void __launch_bounds__(128)
gather_kernel(const float* __restrict__ input,
              float* __restrict__ out,
              int n_out)
{
    const float scale = 0.125f;   // 1 / POOL_VOLUME

    long long gid = (long long)blockIdx.x * blockDim.x + threadIdx.x;
    int o = (int)(gid >> 4);      // output row
    int c = (int)(gid & 15);      // float4 chunk (0..15)
    if (o >= n_out) return;

    // One 32B sector holds count + 7 indices: both int4 loads hit the same
    // sector -> single DRAM access, 1 serial metadata level.
    const int4* m4 = reinterpret_cast<const int4*>(g_meta + (size_t)o * 8);
    int4 a = __ldg(m4);
    int4 b = __ldg(m4 + 1);
    int n = a.x;
    int ncap = n > (INLINE_SLOTS + OVF_CAP) ? (INLINE_SLOTS + OVF_CAP) : n;

    const float4* in4 = reinterpret_cast<const float4*>(input);
    float4 acc = make_float4(0.f, 0.f, 0.f, 0.f);

    // Inline slots (covers 95% of rows entirely)
    {
        int m = ncap;
        bool q0 = (m > 0), q1 = (m > 1), q2 = (m > 2), q3 = (m > 3);
        bool q4 = (m > 4), q5 = (m > 5), q6 = (m > 6);
        float4 v0, v1, v2, v3, v4, v5, v6;
        if (q0) v0 = __ldg(in4 + (size_t)a.y * 16 + c);
        if (q1) v1 = __ldg(in4 + (size_t)a.z * 16 + c);
        if (q2) v2 = __ldg(in4 + (size_t)a.w * 16 + c);
        if (q3) v3 = __ldg(in4 + (size_t)b.x * 16 + c);
        if (q4) v4 = __ldg(in4 + (size_t)b.y * 16 + c);
        if (q5) v5 = __ldg(in4 + (size_t)b.z * 16 + c);
        if (q6) v6 = __ldg(in4 + (size_t)b.w * 16 + c);
        if (q0) { acc.x += v0.x; acc.y += v0.y; acc.z += v0.z; acc.w += v0.w; }
        if (q1) { acc.x += v1.x; acc.y += v1.y; acc.z += v1.z; acc.w += v1.w; }
        if (q2) { acc.x += v2.x; acc.y += v2.y; acc.z += v2.z; acc.w += v2.w; }
        if (q3) { acc.x += v3.x; acc.y += v3.y; acc.z += v3.z; acc.w += v3.w; }
        if (q4) { acc.x += v4.x; acc.y += v4.y; acc.z += v4.z; acc.w += v4.w; }
        if (q5) { acc.x += v5.x; acc.y += v5.y; acc.z += v5.z; acc.w += v5.w; }
        if (q6) { acc.x += v6.x; acc.y += v6.y; acc.z += v6.z; acc.w += v6.w; }
    }

    // Overflow (P ~ 5% of rows)
    if (ncap > INLINE_SLOTS) {
        const int4* ov4 = reinterpret_cast<const int4*>(g_ovf + (size_t)o * OVF_CAP);
        int rem = ncap - INLINE_SLOTS;      // 1..24
        for (int base = 0; base < rem; base += 4) {
            int4 idx = __ldg(ov4 + (base >> 2));
            int m = rem - base;
            bool p1 = (m > 1), p2 = (m > 2), p3 = (m > 3);
            float4 v0, v1, v2, v3;
            v0 = __ldg(in4 + (size_t)idx.x * 16 + c);
            if (p1) v1 = __ldg(in4 + (size_t)idx.y * 16 + c);
            if (p2) v2 = __ldg(in4 + (size_t)idx.z * 16 + c);
            if (p3) v3 = __ldg(in4 + (size_t)idx.w * 16 + c);
            acc.x += v0.x; acc.y += v0.y; acc.z += v0.z; acc.w += v0.w;
            if (p1) { acc.x += v1.x; acc.y += v1.y; acc.z += v1.z; acc.w += v1.w; }
            if (p2) { acc.x += v2.x; acc.y += v2.y; acc.z += v2.z; acc.w += v2.w; }
            if (p3) { acc.x += v3.x; acc.y += v3.y; acc.z += v3.z; acc.w += v3.w; }
        }
    }

    acc.x *= scale; acc.y *= scale; acc.z *= scale; acc.w *= scale;
    __stcs(reinterpret_cast<float4*>(out + (size_t)o * 64) + c, acc);
}

// Fallback path (direct atomic scatter) if sizes exceed scratch capacity.
__global__ void avgpool_scatter_kernel(const float* __restrict__ input,
                                       const int* __restrict__ rules_in,
                                       const int* __restrict__ rules_out,
                                       float* __restrict__ out,
                                       int n_rules)
{
    const float scale = 0.125f;
    long long gid = (long long)blockIdx.x * blockDim.x + threadIdx.x;
    long long total = (long long)n_rules * 16;
    if (gid >= total) return;
    int r = (int)(gid >> 4);
    int c = (int)(gid & 15);
    int rin = rules_in[r];
    int rout = rules_out[r];
    const float4* src = reinterpret_cast<const float4*>(input + (long long)rin * 64) + c;
    float4 v = *src;
    v.x *= scale; v.y *= scale; v.z *= scale; v.w *= scale;
    float* dst = out + (long long)rout * 64 + c * 4;
    asm volatile("red.global.add.v4.f32 [%0], {%1, %2, %3, %4};"
                 :: "l"(dst), "f"(v.x), "f"(v.y), "f"(v.z), "f"(v.w) : "memory");
}

extern "C" void kernel_launch(void* const* d_in, const int* in_sizes, int n_in,
                              void* d_out, int out_size)
{
    const float* input     = (const float*)d_in[0];
    const int*   rules_in  = (const int*)d_in[1];
    const int*   rules_out = (const int*)d_in[2];
    float* out = (float*)d_out;

    int n_rules = in_sizes[1];
    int n_out   = out_size / 64;

    if (n_out > NOUT_CAP || n_rules > NRULE_CAP) {
        cudaMemsetAsync(out, 0, (size_t)out_size * sizeof(float));
        long long total = (long long)n_rules * 16;
        int threads = 256;
        long long blocks = (total + threads - 1) / threads;
        avgpool_scatter_kernel<<<(unsigned)blocks, threads>>>(
            input, rules_in, rules_out, out, n_rules);
        return;
    }

    // Phase A: zero meta (count + inline slots) via a memset node (~12MB).
    {
        void* meta_ptr = nullptr;
        cudaGetSymbolAddress(&meta_ptr, g_meta);
        cudaMemsetAsync(meta_ptr, 0, (size_t)n_out * 8 * sizeof(int));
    }

    // Phase B: invert rulebook (4 rules per thread)
    {
        int n_t = (n_rules + 3) / 4;
        int threads = 256;
        int blocks = (n_t + threads - 1) / threads;
        bucket_scatter_kernel<<<blocks, threads>>>(rules_in, rules_out, n_rules);
    }

    // Phase C: gather (16 threads/row, 128-thread blocks)
    {
        long long total = (long long)n_out * 16;
        int threads = 128;
        long long blocks = (total + threads - 1) / threads;
        gather_kernel<<<(unsigned)blocks, threads>>>(input, out, n_out);
    }
}